// round 14
// baseline (speedup 1.0000x reference)
#include <cuda_runtime.h>
#include <cuda_bf16.h>
#include <math.h>

#define T_ 16
#define B_ 32
#define S_ 256
#define H_ 256
#define E_ 300
#define V_ 1000

// ---------------- scratch arena (floats) ----------------
#define OFF_XPROJ   153600      // [T*B, 4H] = 512*1024
#define OFF_H       710656      // 32*256
#define OFF_ENCT    727040      // 8192*256
#define OFF_COMB    3086336     // 512*512
#define OFF_LOGITS  3348480     // 512*1000
#define SCRATCH_N   3860480

__device__ float g_scratch[SCRATCH_N];
__device__ unsigned int g_flags[128];

// ==================== tf32 mma helpers ====================
__device__ __forceinline__ unsigned f2tf(float x) {
    unsigned r; asm("cvt.rna.tf32.f32 %0, %1;" : "=r"(r) : "f"(x)); return r;
}
__device__ __forceinline__ void mma8(float* c, const unsigned* a, const unsigned* b) {
    asm("mma.sync.aligned.m16n8k8.row.col.f32.tf32.tf32.f32 "
        "{%0,%1,%2,%3}, {%4,%5,%6,%7}, {%8,%9}, {%0,%1,%2,%3};"
        : "+f"(c[0]), "+f"(c[1]), "+f"(c[2]), "+f"(c[3])
        : "r"(a[0]), "r"(a[1]), "r"(a[2]), "r"(a[3]), "r"(b[0]), "r"(b[1]));
}

// store 8 cvt'd floats into transposed smem tile [k][m]
#define STS8(DST, BUF, SK, SM, V0, V1)                  \
    DST[BUF][(SK) + 0][SM] = f2tf((V0).x);              \
    DST[BUF][(SK) + 1][SM] = f2tf((V0).y);              \
    DST[BUF][(SK) + 2][SM] = f2tf((V0).z);              \
    DST[BUF][(SK) + 3][SM] = f2tf((V0).w);              \
    DST[BUF][(SK) + 4][SM] = f2tf((V1).x);              \
    DST[BUF][(SK) + 5][SM] = f2tf((V1).y);              \
    DST[BUF][(SK) + 6][SM] = f2tf((V1).z);              \
    DST[BUF][(SK) + 7][SM] = f2tf((V1).w);

// 64x64x32 tile, 4 warps (128 thr): warp = 32x32 quadrant (mi=2, ni=4)
#define MMA_TILE32(CUR)                                                      \
    _Pragma("unroll")                                                        \
    for (int s = 0; s < 4; s++) {                                            \
        unsigned af[2][4], bf[4][2];                                         \
        _Pragma("unroll")                                                    \
        for (int mi = 0; mi < 2; mi++) {                                     \
            af[mi][0] = AsT[CUR][s * 8 + j    ][m_off + mi * 16 + g];        \
            af[mi][1] = AsT[CUR][s * 8 + j    ][m_off + mi * 16 + g + 8];    \
            af[mi][2] = AsT[CUR][s * 8 + j + 4][m_off + mi * 16 + g];        \
            af[mi][3] = AsT[CUR][s * 8 + j + 4][m_off + mi * 16 + g + 8];    \
        }                                                                    \
        _Pragma("unroll")                                                    \
        for (int ni = 0; ni < 4; ni++) {                                     \
            bf[ni][0] = BsT[CUR][s * 8 + j    ][n_off + ni * 8 + g];         \
            bf[ni][1] = BsT[CUR][s * 8 + j + 4][n_off + ni * 8 + g];         \
        }                                                                    \
        _Pragma("unroll")                                                    \
        for (int mi = 0; mi < 2; mi++)                                       \
            _Pragma("unroll")                                                \
            for (int ni = 0; ni < 4; ni++)                                   \
                mma8(cacc[mi][ni], af[mi], bf[ni]);                          \
    }

// 64x64x32 tile, 8 warps (256 thr): warp = 16x32 sub-tile (mi=1, ni=4)
#define MMA_TILE32_W8(CUR)                                                   \
    _Pragma("unroll")                                                        \
    for (int s = 0; s < 4; s++) {                                            \
        unsigned af[4], bf[4][2];                                            \
        af[0] = AsT[CUR][s * 8 + j    ][m_off + g];                          \
        af[1] = AsT[CUR][s * 8 + j    ][m_off + g + 8];                      \
        af[2] = AsT[CUR][s * 8 + j + 4][m_off + g];                          \
        af[3] = AsT[CUR][s * 8 + j + 4][m_off + g + 8];                      \
        _Pragma("unroll")                                                    \
        for (int ni = 0; ni < 4; ni++) {                                     \
            bf[ni][0] = BsT[CUR][s * 8 + j    ][n_off + ni * 8 + g];         \
            bf[ni][1] = BsT[CUR][s * 8 + j + 4][n_off + ni * 8 + g];         \
        }                                                                    \
        _Pragma("unroll")                                                    \
        for (int ni = 0; ni < 4; ni++)                                       \
            mma8(cacc[ni], af, bf[ni]);                                      \
    }

// ============================================================================
// xproj tf32 GEMM (standalone): emb[tv] @ W_ih^T + b_ih  (M=512,N=1024,K=300)
// 128 blocks x 128 threads, 64x64x32 tiles. (validated R12 body)
// ============================================================================
__global__ void xproj_gemm_k(const float* __restrict__ emb, const int* __restrict__ tv,
                             const float* __restrict__ W_ih, const float* __restrict__ b_ih,
                             float* __restrict__ xproj) {
    __shared__ unsigned AsT[2][32][65];
    __shared__ unsigned BsT[2][32][65];
    __shared__ int rows_sh[64];

    int tid = threadIdx.x;
    int lane = tid & 31, warp = tid >> 5;
    int g = lane >> 2, j = lane & 3;
    int m_off = (warp & 1) * 32, n_off = (warp >> 1) * 32;
    int sm = tid >> 1, sk = (tid & 1) * 16;
    int bid = blockIdx.x;
    int m0 = (bid >> 4) * 64, n0 = (bid & 15) * 64;

    float cacc[2][4][4];
    #pragma unroll
    for (int mi = 0; mi < 2; mi++)
        #pragma unroll
        for (int ni = 0; ni < 4; ni++)
            #pragma unroll
            for (int q = 0; q < 4; q++) cacc[mi][ni][q] = 0.f;

    if (tid < 64) rows_sh[tid] = tv[m0 + tid];
    __syncthreads();
    {
        const float4* ap = reinterpret_cast<const float4*>(emb + (long)rows_sh[sm] * E_ + sk);
        const float4* bp = reinterpret_cast<const float4*>(W_ih + (long)(n0 + sm) * E_ + sk);
        float4 a0 = ap[0], a1 = ap[1], a2 = ap[2], a3 = ap[3];
        float4 b0 = bp[0], b1 = bp[1], b2 = bp[2], b3 = bp[3];
        STS8(AsT, 0, sk, sm, a0, a1); STS8(AsT, 0, sk + 8, sm, a2, a3);
        STS8(BsT, 0, sk, sm, b0, b1); STS8(BsT, 0, sk + 8, sm, b2, b3);
    }
    __syncthreads();
    for (int kt = 0; kt < 10; kt++) {
        int cur = kt & 1, nxt = cur ^ 1;
        bool more = (kt + 1 < 10);
        float4 va[4], vb[4];
        if (more) {
            int gk = (kt + 1) * 32 + sk;
            if ((kt + 2) * 32 <= E_) {
                const float4* ap = reinterpret_cast<const float4*>(emb + (long)rows_sh[sm] * E_ + gk);
                const float4* bp = reinterpret_cast<const float4*>(W_ih + (long)(n0 + sm) * E_ + gk);
                va[0] = ap[0]; va[1] = ap[1]; va[2] = ap[2]; va[3] = ap[3];
                vb[0] = bp[0]; vb[1] = bp[1]; vb[2] = bp[2]; vb[3] = bp[3];
            } else {
                const float* ar = emb + (long)rows_sh[sm] * E_;
                const float* br = W_ih + (long)(n0 + sm) * E_;
                float t[16], u[16];
                #pragma unroll
                for (int i = 0; i < 16; i++) {
                    int k = gk + i;
                    t[i] = (k < E_) ? ar[k] : 0.f;
                    u[i] = (k < E_) ? br[k] : 0.f;
                }
                #pragma unroll
                for (int q = 0; q < 4; q++) {
                    va[q] = make_float4(t[4*q], t[4*q+1], t[4*q+2], t[4*q+3]);
                    vb[q] = make_float4(u[4*q], u[4*q+1], u[4*q+2], u[4*q+3]);
                }
            }
        }
        MMA_TILE32(cur);
        if (more) {
            STS8(AsT, nxt, sk, sm, va[0], va[1]); STS8(AsT, nxt, sk + 8, sm, va[2], va[3]);
            STS8(BsT, nxt, sk, sm, vb[0], vb[1]); STS8(BsT, nxt, sk + 8, sm, vb[2], vb[3]);
        }
        __syncthreads();
    }
    #pragma unroll
    for (int mi = 0; mi < 2; mi++) {
        int rm = m0 + m_off + mi * 16;
        #pragma unroll
        for (int ni = 0; ni < 4; ni++) {
            int cn = n0 + n_off + ni * 8 + 2 * j;
            float2 p0 = make_float2(cacc[mi][ni][0] + b_ih[cn], cacc[mi][ni][1] + b_ih[cn + 1]);
            float2 p1 = make_float2(cacc[mi][ni][2] + b_ih[cn], cacc[mi][ni][3] + b_ih[cn + 1]);
            *reinterpret_cast<float2*>(xproj + (long)(rm + g) * (4 * H_) + cn) = p0;
            *reinterpret_cast<float2*>(xproj + (long)(rm + g + 8) * (4 * H_) + cn) = p1;
        }
    }
}

// ============================================================================
// Fused persistent LSTM + enc_t GEMM. 640 blocks x 256 threads.
// blocks [0,128):   LSTM (16 groups x 8; co-resident: first wave, 1 block/SM)
// blocks [128,640): enc_t = enc @ We^T + be  (M=8192,N=256,K=256) tf32
// ============================================================================
#define LSTM_GRID_TOTAL 640
#define WSTRIDE 129
#define LSTM_SMEM ((64 * WSTRIDE + 128) * 16 + 2 * 256 * 4)

__global__ void lstm_enc_k(const float* __restrict__ h0,
                           const float* __restrict__ c0,
                           const float* __restrict__ xproj,
                           const float* __restrict__ W_hh,
                           const float* __restrict__ b_hh,
                           float* __restrict__ h_glob,
                           float* __restrict__ comb,
                           float* __restrict__ o_hT,
                           float* __restrict__ o_cT,
                           const float* __restrict__ enc,
                           const float* __restrict__ We,
                           const float* __restrict__ be,
                           float* __restrict__ enct) {
    extern __shared__ unsigned char smraw[];

    if (blockIdx.x < 128) {
        // ================= LSTM (validated R12 body) =======================
        float4* w4s = reinterpret_cast<float4*>(smraw);     // [64][WSTRIDE]
        float4* h4s = w4s + 64 * WSTRIDE;                   // [2][64]
        float*  part = (float*)(h4s + 128);                 // [2][256]

        int tid = threadIdx.x;
        int grp = blockIdx.x >> 3;
        int blk = blockIdx.x & 7;

        const float4* W4 = reinterpret_cast<const float4*>(W_hh);
        for (int idx = tid; idx < 128 * 64; idx += 256) {
            int c = idx >> 6, k4 = idx & 63;
            int gcol = (c >> 5) * 256 + blk * 32 + (c & 31);
            w4s[k4 * WSTRIDE + c] = W4[(long)gcol * 64 + k4];
        }

        int pu = tid & 31, pbl = tid >> 5;
        int hh = blk * 32 + pu;
        int bb = grp * 2 + pbl;
        float c_reg = 0.f, bh0 = 0.f, bh1 = 0.f, bh2 = 0.f, bh3 = 0.f;
        if (tid < 64) {
            c_reg = c0[bb * H_ + hh];
            bh0 = b_hh[hh];           bh1 = b_hh[H_ + hh];
            bh2 = b_hh[2 * H_ + hh];  bh3 = b_hh[3 * H_ + hh];
        }

        int col = tid & 127, kh = tid >> 7;
        int kbase = kh * 32;
        volatile unsigned int* flags = g_flags;

        for (int t = 0; t < T_; t++) {
            if (t > 0) {
                if (tid < 8) {
                    unsigned int tgt = (unsigned int)t;
                    while (flags[grp * 8 + tid] < tgt) {}
                }
            }
            __syncthreads();

            const float* hsrc = (t == 0) ? h0 : h_glob;
            if (tid < 128) {
                int b = tid >> 6, k4 = tid & 63;
                h4s[b * 64 + k4] =
                    __ldcg(reinterpret_cast<const float4*>(hsrc + (grp * 2 + b) * H_) + k4);
            }
            float xg0 = 0.f, xg1 = 0.f, xg2 = 0.f, xg3 = 0.f;
            if (tid < 64) {
                const float* xp = xproj + (long)(t * B_ + bb) * (4 * H_);
                xg0 = xp[hh]; xg1 = xp[H_ + hh]; xg2 = xp[2 * H_ + hh]; xg3 = xp[3 * H_ + hh];
            }
            __syncthreads();

            {
                float4 p0 = make_float4(0.f, 0.f, 0.f, 0.f);
                float4 p1 = make_float4(0.f, 0.f, 0.f, 0.f);
                const float4* hb0 = h4s;
                const float4* hb1 = h4s + 64;
                #pragma unroll 8
                for (int k4 = 0; k4 < 32; k4++) {
                    float4 w = w4s[(kbase + k4) * WSTRIDE + col];
                    float4 ha = hb0[kbase + k4];
                    float4 hbv = hb1[kbase + k4];
                    p0.x = fmaf(w.x, ha.x, p0.x);
                    p0.y = fmaf(w.y, ha.y, p0.y);
                    p0.z = fmaf(w.z, ha.z, p0.z);
                    p0.w = fmaf(w.w, ha.w, p0.w);
                    p1.x = fmaf(w.x, hbv.x, p1.x);
                    p1.y = fmaf(w.y, hbv.y, p1.y);
                    p1.z = fmaf(w.z, hbv.z, p1.z);
                    p1.w = fmaf(w.w, hbv.w, p1.w);
                }
                part[kh * 256 + col * 2 + 0] = (p0.x + p0.y) + (p0.z + p0.w);
                part[kh * 256 + col * 2 + 1] = (p1.x + p1.y) + (p1.z + p1.w);
            }
            __syncthreads();

            if (tid < 64) {
                int i0 = (0 * 32 + pu) * 2 + pbl;
                int i1 = (1 * 32 + pu) * 2 + pbl;
                int i2 = (2 * 32 + pu) * 2 + pbl;
                int i3 = (3 * 32 + pu) * 2 + pbl;
                float gi = part[i0] + part[256 + i0] + xg0 + bh0;
                float gf = part[i1] + part[256 + i1] + xg1 + bh1;
                float gg = part[i2] + part[256 + i2] + xg2 + bh2;
                float go = part[i3] + part[256 + i3] + xg3 + bh3;
                float si = 1.f / (1.f + __expf(-gi));
                float sf = 1.f / (1.f + __expf(-gf));
                float so = 1.f / (1.f + __expf(-go));
                c_reg = sf * c_reg + si * tanhf(gg);
                float hn = so * tanhf(c_reg);
                h_glob[bb * H_ + hh] = hn;
                comb[(long)(t * B_ + bb) * (2 * H_) + H_ + hh] = hn;
                if (t == T_ - 1) {
                    o_hT[bb * H_ + hh] = hn;
                    o_cT[bb * H_ + hh] = c_reg;
                }
            }

            if (t < T_ - 1) {
                __syncthreads();
                if (tid == 0) {
                    __threadfence();
                    g_flags[blockIdx.x] = (unsigned int)(t + 1);
                }
            }
        }
    } else {
        // ============ enc_t GEMM, 256 threads (8 warps, mi=1/ni=4) =========
        typedef unsigned tile_t[32][65];
        tile_t* AsT = reinterpret_cast<tile_t*>(smraw);
        tile_t* BsT = reinterpret_cast<tile_t*>(smraw + 2 * 32 * 65 * 4);

        int tid = threadIdx.x;
        int lane = tid & 31, warp = tid >> 5;
        int g = lane >> 2, j = lane & 3;
        int m_off = (warp & 3) * 16, n_off = (warp >> 2) * 32;
        int sm = tid >> 2, sk = (tid & 3) * 8;
        int r2 = blockIdx.x - 128;
        int m0 = (r2 >> 2) * 64, n0 = (r2 & 3) * 64;

        float cacc[4][4];
        #pragma unroll
        for (int ni = 0; ni < 4; ni++)
            #pragma unroll
            for (int q = 0; q < 4; q++) cacc[ni][q] = 0.f;

        {
            const float4* ap = reinterpret_cast<const float4*>(enc + (long)(m0 + sm) * H_ + sk);
            const float4* bp = reinterpret_cast<const float4*>(We + (long)(n0 + sm) * H_ + sk);
            float4 a0 = ap[0], a1 = ap[1], b0 = bp[0], b1 = bp[1];
            STS8(AsT, 0, sk, sm, a0, a1);
            STS8(BsT, 0, sk, sm, b0, b1);
        }
        __syncthreads();
        for (int kt = 0; kt < 8; kt++) {
            int cur = kt & 1, nxt = cur ^ 1;
            bool more = (kt + 1 < 8);
            float4 va0, va1, vb0, vb1;
            if (more) {
                int gk = (kt + 1) * 32 + sk;
                const float4* ap = reinterpret_cast<const float4*>(enc + (long)(m0 + sm) * H_ + gk);
                const float4* bp = reinterpret_cast<const float4*>(We + (long)(n0 + sm) * H_ + gk);
                va0 = ap[0]; va1 = ap[1]; vb0 = bp[0]; vb1 = bp[1];
            }
            MMA_TILE32_W8(cur);
            if (more) {
                STS8(AsT, nxt, sk, sm, va0, va1);
                STS8(BsT, nxt, sk, sm, vb0, vb1);
            }
            __syncthreads();
        }
        int rm = m0 + m_off;
        #pragma unroll
        for (int ni = 0; ni < 4; ni++) {
            int cn = n0 + n_off + ni * 8 + 2 * j;
            float2 p0 = make_float2(cacc[ni][0] + be[cn], cacc[ni][1] + be[cn + 1]);
            float2 p1 = make_float2(cacc[ni][2] + be[cn], cacc[ni][3] + be[cn + 1]);
            *reinterpret_cast<float2*>(enct + (long)(rm + g) * H_ + cn) = p0;
            *reinterpret_cast<float2*>(enct + (long)(rm + g + 8) * H_ + cn) = p1;
        }
    }
}

// ============ logits tf32 GEMM: 256 threads, M=512,N=1000,K=512 =============
__global__ void logits_gemm_k(const float* __restrict__ A,      // comb, lda=512
                              const float* __restrict__ Bm,     // W_out [1000,512]
                              const float* __restrict__ bias,
                              float* __restrict__ C) {          // [512,1000]
    __shared__ unsigned AsT[2][32][65];
    __shared__ unsigned BsT[2][32][65];

    int tid = threadIdx.x;
    int lane = tid & 31, warp = tid >> 5;
    int g = lane >> 2, j = lane & 3;
    int m_off = (warp & 3) * 16, n_off = (warp >> 2) * 32;
    int sm = tid >> 2, sk = (tid & 3) * 8;
    int m0 = blockIdx.y * 64, n0 = blockIdx.x * 64;
    bool bn_ok = (n0 + sm) < V_;

    float cacc[4][4];
    #pragma unroll
    for (int ni = 0; ni < 4; ni++)
        #pragma unroll
        for (int q = 0; q < 4; q++) cacc[ni][q] = 0.f;

    {
        const float4* ap = reinterpret_cast<const float4*>(A + (long)(m0 + sm) * (2 * H_) + sk);
        float4 a0 = ap[0], a1 = ap[1];
        float4 z = make_float4(0.f, 0.f, 0.f, 0.f);
        float4 b0 = z, b1 = z;
        if (bn_ok) {
            const float4* bp = reinterpret_cast<const float4*>(Bm + (long)(n0 + sm) * (2 * H_) + sk);
            b0 = bp[0]; b1 = bp[1];
        }
        STS8(AsT, 0, sk, sm, a0, a1);
        STS8(BsT, 0, sk, sm, b0, b1);
    }
    __syncthreads();
    for (int kt = 0; kt < 16; kt++) {
        int cur = kt & 1, nxt = cur ^ 1;
        bool more = (kt + 1 < 16);
        float4 va0, va1, vb0, vb1;
        if (more) {
            int gk = (kt + 1) * 32 + sk;
            const float4* ap = reinterpret_cast<const float4*>(A + (long)(m0 + sm) * (2 * H_) + gk);
            va0 = ap[0]; va1 = ap[1];
            float4 z = make_float4(0.f, 0.f, 0.f, 0.f);
            vb0 = z; vb1 = z;
            if (bn_ok) {
                const float4* bp = reinterpret_cast<const float4*>(Bm + (long)(n0 + sm) * (2 * H_) + gk);
                vb0 = bp[0]; vb1 = bp[1];
            }
        }
        MMA_TILE32_W8(cur);
        if (more) {
            STS8(AsT, nxt, sk, sm, va0, va1);
            STS8(BsT, nxt, sk, sm, vb0, vb1);
        }
        __syncthreads();
    }
    int rm = m0 + m_off;
    #pragma unroll
    for (int ni = 0; ni < 4; ni++) {
        int cn = n0 + n_off + ni * 8 + 2 * j;
        if (cn + 1 < V_) {
            float2 p0 = make_float2(cacc[ni][0] + bias[cn], cacc[ni][1] + bias[cn + 1]);
            float2 p1 = make_float2(cacc[ni][2] + bias[cn], cacc[ni][3] + bias[cn + 1]);
            *reinterpret_cast<float2*>(C + (long)(rm + g) * V_ + cn) = p0;
            *reinterpret_cast<float2*>(C + (long)(rm + g + 8) * V_ + cn) = p1;
        }
    }
}

// ========== fused attention: dec matvec + scores + softmax + context ========
__device__ __forceinline__ float tanh_fast(float x) {
    float y;
    asm("tanh.approx.f32 %0, %1;" : "=f"(y) : "f"(x));
    return y;
}

__global__ void attn_fused_k(const float* __restrict__ enc_t,
                             const float* __restrict__ Wd,
                             const float* __restrict__ bd,
                             const float* __restrict__ wa,
                             const float* __restrict__ ba,
                             const int* __restrict__ lens,
                             const float* __restrict__ enc,
                             float* __restrict__ comb,
                             float* __restrict__ ctx_out) {
    int t = blockIdx.x / B_, b = blockIdx.x % B_;
    __shared__ float out_sh[H_], dec_sh[H_], wa_sh[H_], sc[S_], red[S_];
    int tid = threadIdx.x;
    int wrp = tid >> 5, lane = tid & 31;

    out_sh[tid] = comb[(long)(t * B_ + b) * (2 * H_) + H_ + tid];
    wa_sh[tid] = wa[tid];
    __syncthreads();

    {
        const float4* o4 = reinterpret_cast<const float4*>(out_sh);
        float4 oa = o4[lane], ob = o4[lane + 32];
        #pragma unroll 4
        for (int i = 0; i < 32; i++) {
            int hh = wrp * 32 + i;
            const float4* wr = reinterpret_cast<const float4*>(Wd + (long)hh * H_);
            float4 w0 = wr[lane], w1 = wr[lane + 32];
            float s = oa.x * w0.x + oa.y * w0.y + oa.z * w0.z + oa.w * w0.w
                    + ob.x * w1.x + ob.y * w1.y + ob.z * w1.z + ob.w * w1.w;
            #pragma unroll
            for (int o = 16; o; o >>= 1) s += __shfl_xor_sync(0xffffffffu, s, o);
            if (lane == 0) dec_sh[hh] = s + bd[hh];
        }
    }
    __syncthreads();

    float bav = ba[0];
    for (int s = wrp; s < S_; s += 8) {
        const float* er = enc_t + (long)(s * B_ + b) * H_;
        float sum = 0.f;
        #pragma unroll
        for (int i = 0; i < 8; i++) {
            int hh = lane + 32 * i;
            sum += tanh_fast(er[hh] + dec_sh[hh]) * wa_sh[hh];
        }
        #pragma unroll
        for (int o = 16; o; o >>= 1) sum += __shfl_xor_sync(0xffffffffu, sum, o);
        if (lane == 0) sc[s] = sum + bav;
    }
    __syncthreads();

    int len = lens[b];
    float v = (tid < len) ? sc[tid] : -1e30f;
    red[tid] = v; __syncthreads();
    for (int o = 128; o; o >>= 1) { if (tid < o) red[tid] = fmaxf(red[tid], red[tid + o]); __syncthreads(); }
    float m = red[0]; __syncthreads();
    float e = __expf(v - m);
    red[tid] = e; __syncthreads();
    for (int o = 128; o; o >>= 1) { if (tid < o) red[tid] += red[tid + o]; __syncthreads(); }
    float p = e * __fdividef(1.f, red[0]);
    __syncthreads();
    sc[tid] = p;
    __syncthreads();

    float sum = 0.f;
    const float* ep = enc + b * H_ + tid;
    #pragma unroll 4
    for (int s = 0; s < S_; s++)
        sum = fmaf(sc[s], ep[(long)s * B_ * H_], sum);
    comb[(long)(t * B_ + b) * (2 * H_) + tid] = sum;
    ctx_out[(long)(b * T_ + t) * H_ + tid] = sum;
}

// ---------------- softmax over V=1000 ----------------
__global__ void softmax_v_k(const float* __restrict__ logits, float* __restrict__ out) {
    int tb = blockIdx.x;
    int tid = threadIdx.x;
    __shared__ float red[256];
    const float* row = logits + (long)tb * V_;
    float m = -1e30f;
    for (int v = tid; v < V_; v += 256) m = fmaxf(m, row[v]);
    red[tid] = m; __syncthreads();
    for (int o = 128; o; o >>= 1) { if (tid < o) red[tid] = fmaxf(red[tid], red[tid + o]); __syncthreads(); }
    m = red[0]; __syncthreads();
    float sum = 0.f;
    for (int v = tid; v < V_; v += 256) {
        float e = __expf(row[v] - m);
        out[(long)tb * V_ + v] = e;
        sum += e;
    }
    red[tid] = sum; __syncthreads();
    for (int o = 128; o; o >>= 1) { if (tid < o) red[tid] += red[tid + o]; __syncthreads(); }
    float inv = __fdividef(1.f, red[0]);
    for (int v = tid; v < V_; v += 256) out[(long)tb * V_ + v] *= inv;
}

// ---------------- host ----------------
extern "C" void kernel_launch(void* const* d_in, const int* in_sizes, int n_in,
                              void* d_out, int out_size) {
    const int*   tv      = (const int*)  d_in[0];
    const float* h0      = (const float*)d_in[1];
    const float* c0      = (const float*)d_in[2];
    const float* enc     = (const float*)d_in[3];
    const int*   lens    = (const int*)  d_in[4];
    const float* emb     = (const float*)d_in[5];
    const float* W_ih    = (const float*)d_in[6];
    const float* W_hh    = (const float*)d_in[7];
    const float* b_ih    = (const float*)d_in[8];
    const float* b_hh    = (const float*)d_in[9];
    const float* We      = (const float*)d_in[10];
    const float* be      = (const float*)d_in[11];
    const float* Wd      = (const float*)d_in[12];
    const float* bd      = (const float*)d_in[13];
    const float* wa      = (const float*)d_in[14];
    const float* ba      = (const float*)d_in[15];
    const float* W_out   = (const float*)d_in[16];
    const float* b_out   = (const float*)d_in[17];

    float* scratch = nullptr;
    cudaGetSymbolAddress((void**)&scratch, g_scratch);
    unsigned int* flagsp = nullptr;
    cudaGetSymbolAddress((void**)&flagsp, g_flags);

    float* s_xproj  = scratch + OFF_XPROJ;
    float* s_h      = scratch + OFF_H;
    float* s_enct   = scratch + OFF_ENCT;
    float* s_comb   = scratch + OFF_COMB;
    float* s_logits = scratch + OFF_LOGITS;

    float* o_prob = (float*)d_out;
    float* o_hT   = o_prob + (long)T_ * B_ * V_;
    float* o_cT   = o_hT + B_ * H_;
    float* o_ctx  = o_cT + B_ * H_;

    // 0) reset group-barrier flags
    cudaMemsetAsync(flagsp, 0, 128 * sizeof(unsigned int));

    // 1) xproj GEMM (LSTM input only -> shortest path to LSTM start)
    xproj_gemm_k<<<128, 128>>>(emb, tv, W_ih, b_ih, s_xproj);

    // 2) fused: persistent LSTM (blocks 0-127) + enc_t GEMM (blocks 128-639)
    cudaFuncSetAttribute(lstm_enc_k, cudaFuncAttributeMaxDynamicSharedMemorySize, LSTM_SMEM);
    lstm_enc_k<<<LSTM_GRID_TOTAL, 256, LSTM_SMEM>>>(h0, c0, s_xproj, W_hh, b_hh,
                                                    s_h, s_comb, o_hT, o_cT,
                                                    enc, We, be, s_enct);

    // 3) fused attention: dec matvec + scores + masked softmax + context
    attn_fused_k<<<T_ * B_, 256>>>(s_enct, Wd, bd, wa, ba, lens, enc, s_comb, o_ctx);

    // 4) logits = combined @ W_out^T + b_out : [512, 1000] (tf32, 256 thr)
    logits_gemm_k<<<dim3(16, 8), 256>>>(s_comb, W_out, b_out, s_logits);

    // 5) softmax over V -> output_prob
    softmax_v_k<<<T_ * B_, 256>>>(s_logits, o_prob);
}

// round 15
// speedup vs baseline: 1.1887x; 1.1887x over previous
#include <cuda_runtime.h>
#include <cuda_bf16.h>
#include <math.h>

#define T_ 16
#define B_ 32
#define S_ 256
#define H_ 256
#define E_ 300
#define V_ 1000

// ---------------- scratch arena (floats) ----------------
#define OFF_XPROJ   153600      // [T*B, 4H] = 512*1024
#define OFF_H       710656      // 32*256
#define OFF_ENCT    727040      // 8192*256
#define OFF_COMB    3086336     // 512*512
#define OFF_LOGITS  3348480     // 512*1000
#define SCRATCH_N   3860480

__device__ float g_scratch[SCRATCH_N];
__device__ unsigned int g_flags[128];

// ==================== tf32 mma + cp.async helpers ====================
__device__ __forceinline__ void mma8(float* c, const unsigned* a, const unsigned* b) {
    asm("mma.sync.aligned.m16n8k8.row.col.f32.tf32.tf32.f32 "
        "{%0,%1,%2,%3}, {%4,%5,%6,%7}, {%8,%9}, {%0,%1,%2,%3};"
        : "+f"(c[0]), "+f"(c[1]), "+f"(c[2]), "+f"(c[3])
        : "r"(a[0]), "r"(a[1]), "r"(a[2]), "r"(a[3]), "r"(b[0]), "r"(b[1]));
}
__device__ __forceinline__ unsigned sptr(const void* p) {
    return (unsigned)__cvta_generic_to_shared(p);
}
__device__ __forceinline__ void cpa16(unsigned dst, const void* src) {
    asm volatile("cp.async.cg.shared.global [%0], [%1], 16;" :: "r"(dst), "l"(src));
}
__device__ __forceinline__ void cpa16z(unsigned dst, const void* src, unsigned sz) {
    asm volatile("cp.async.cg.shared.global [%0], [%1], 16, %2;" :: "r"(dst), "l"(src), "r"(sz));
}
#define CPA_COMMIT() asm volatile("cp.async.commit_group;" ::: "memory")
#define CPA_WAIT1()  asm volatile("cp.async.wait_group 1;" ::: "memory")
#define CPA_WAIT0()  asm volatile("cp.async.wait_group 0;" ::: "memory")

// 64x64x32 MMA tile from row-major smem [64][36] (raw fp32 bits as tf32).
// 4 warps, warp = 32x32 quadrant (mi=2, ni=4). Locals: g, j, m_off, n_off, cacc.
#define MMA_RM32(AU, BU)                                                     \
    _Pragma("unroll")                                                        \
    for (int s = 0; s < 4; s++) {                                            \
        unsigned af[2][4], bf[4][2];                                         \
        _Pragma("unroll")                                                    \
        for (int mi = 0; mi < 2; mi++) {                                     \
            int r0 = (m_off + mi * 16 + g) * 36 + s * 8 + j;                 \
            int r1 = (m_off + mi * 16 + g + 8) * 36 + s * 8 + j;             \
            af[mi][0] = (AU)[r0];                                            \
            af[mi][1] = (AU)[r1];                                            \
            af[mi][2] = (AU)[r0 + 4];                                        \
            af[mi][3] = (AU)[r1 + 4];                                        \
        }                                                                    \
        _Pragma("unroll")                                                    \
        for (int ni = 0; ni < 4; ni++) {                                     \
            int rb = (n_off + ni * 8 + g) * 36 + s * 8 + j;                  \
            bf[ni][0] = (BU)[rb];                                            \
            bf[ni][1] = (BU)[rb + 4];                                        \
        }                                                                    \
        _Pragma("unroll")                                                    \
        for (int mi = 0; mi < 2; mi++)                                       \
            _Pragma("unroll")                                                \
            for (int ni = 0; ni < 4; ni++)                                   \
                mma8(cacc[mi][ni], af[mi], bf[ni]);                          \
    }

// ============================================================================
// Dual tf32 GEMM with cp.async pipeline. 640 blocks x 128 threads.
// blocks [0,128):   xproj = emb[tv] @ W_ih^T + b_ih  (M=512,N=1024,K=300)
// blocks [128,640): enc_t = enc @ We^T + be          (M=8192,N=256,K=256)
// ============================================================================
__global__ void dual_gemm_k(const float* __restrict__ emb, const int* __restrict__ tv,
                            const float* __restrict__ W_ih, const float* __restrict__ b_ih,
                            float* __restrict__ xproj,
                            const float* __restrict__ enc, const float* __restrict__ We,
                            const float* __restrict__ be, float* __restrict__ enct) {
    __shared__ __align__(16) float As[2][64][36];
    __shared__ __align__(16) float Bs[2][64][36];
    __shared__ int rows_sh[64];

    int tid = threadIdx.x;
    int lane = tid & 31, warp = tid >> 5;
    int g = lane >> 2, j = lane & 3;
    int m_off = (warp & 1) * 32, n_off = (warp >> 1) * 32;
    int ar = tid >> 1, ac = (tid & 1) * 16;    // load row / float-offset in k-tile
    int bid = blockIdx.x;

    float cacc[2][4][4] = {};

    if (bid < 128) {
        // -------- xproj: K=300, 10 k-tiles (last ragged, zero-filled) -------
        int m0 = (bid >> 4) * 64, n0 = (bid & 15) * 64;
        if (tid < 64) rows_sh[tid] = tv[m0 + tid];
        __syncthreads();
        const float* abase = emb + (long)rows_sh[ar] * E_;
        const float* bbase = W_ih + (long)(n0 + ar) * E_;

#define XP_ISSUE(ST, KT) do {                                                \
            int kb = (KT) * 32 + ac;                                         \
            _Pragma("unroll")                                                \
            for (int q = 0; q < 4; q++) {                                    \
                int k = kb + q * 4;                                          \
                unsigned sz = (k < E_) ? 16u : 0u;                           \
                int ks = (k < E_) ? k : 0;                                   \
                cpa16z(sptr(&As[ST][ar][ac + q * 4]), abase + ks, sz);       \
                cpa16z(sptr(&Bs[ST][ar][ac + q * 4]), bbase + ks, sz);       \
            }                                                                \
            CPA_COMMIT();                                                    \
        } while (0)

        XP_ISSUE(0, 0);
        for (int kt = 0; kt < 10; kt++) {
            int cur = kt & 1, nxt = cur ^ 1;
            if (kt + 1 < 10) { XP_ISSUE(nxt, kt + 1); CPA_WAIT1(); }
            else { CPA_WAIT0(); }
            __syncthreads();
            const unsigned* AU = reinterpret_cast<const unsigned*>(As[cur]);
            const unsigned* BU = reinterpret_cast<const unsigned*>(Bs[cur]);
            MMA_RM32(AU, BU);
            __syncthreads();
        }
        #pragma unroll
        for (int mi = 0; mi < 2; mi++) {
            int rm = m0 + m_off + mi * 16;
            #pragma unroll
            for (int ni = 0; ni < 4; ni++) {
                int cn = n0 + n_off + ni * 8 + 2 * j;
                float2 p0 = make_float2(cacc[mi][ni][0] + b_ih[cn], cacc[mi][ni][1] + b_ih[cn + 1]);
                float2 p1 = make_float2(cacc[mi][ni][2] + b_ih[cn], cacc[mi][ni][3] + b_ih[cn + 1]);
                *reinterpret_cast<float2*>(xproj + (long)(rm + g) * (4 * H_) + cn) = p0;
                *reinterpret_cast<float2*>(xproj + (long)(rm + g + 8) * (4 * H_) + cn) = p1;
            }
        }
    } else {
        // -------- enc_t: K=256, 8 clean k-tiles ----------------------------
        int r2 = bid - 128;
        int m0 = (r2 >> 2) * 64, n0 = (r2 & 3) * 64;
        const float* abase = enc + (long)(m0 + ar) * H_ + ac;
        const float* bbase = We + (long)(n0 + ar) * H_ + ac;

#define EN_ISSUE(ST, KT) do {                                                \
            const float* as = abase + (KT) * 32;                             \
            const float* bsp = bbase + (KT) * 32;                            \
            _Pragma("unroll")                                                \
            for (int q = 0; q < 4; q++) {                                    \
                cpa16(sptr(&As[ST][ar][ac + q * 4]), as + q * 4);            \
                cpa16(sptr(&Bs[ST][ar][ac + q * 4]), bsp + q * 4);           \
            }                                                                \
            CPA_COMMIT();                                                    \
        } while (0)

        EN_ISSUE(0, 0);
        for (int kt = 0; kt < 8; kt++) {
            int cur = kt & 1, nxt = cur ^ 1;
            if (kt + 1 < 8) { EN_ISSUE(nxt, kt + 1); CPA_WAIT1(); }
            else { CPA_WAIT0(); }
            __syncthreads();
            const unsigned* AU = reinterpret_cast<const unsigned*>(As[cur]);
            const unsigned* BU = reinterpret_cast<const unsigned*>(Bs[cur]);
            MMA_RM32(AU, BU);
            __syncthreads();
        }
        #pragma unroll
        for (int mi = 0; mi < 2; mi++) {
            int rm = m0 + m_off + mi * 16;
            #pragma unroll
            for (int ni = 0; ni < 4; ni++) {
                int cn = n0 + n_off + ni * 8 + 2 * j;
                float2 p0 = make_float2(cacc[mi][ni][0] + be[cn], cacc[mi][ni][1] + be[cn + 1]);
                float2 p1 = make_float2(cacc[mi][ni][2] + be[cn], cacc[mi][ni][3] + be[cn + 1]);
                *reinterpret_cast<float2*>(enct + (long)(rm + g) * H_ + cn) = p0;
                *reinterpret_cast<float2*>(enct + (long)(rm + g + 8) * H_ + cn) = p1;
            }
        }
    }
}

// ============ logits tf32 GEMM (cp.async): M=512, N=1000, K=512 =============
__global__ void logits_gemm_k(const float* __restrict__ A,      // comb, lda=512
                              const float* __restrict__ Bm,     // W_out [1000,512]
                              const float* __restrict__ bias,
                              float* __restrict__ C) {          // [512,1000]
    __shared__ __align__(16) float As[2][64][36];
    __shared__ __align__(16) float Bs[2][64][36];

    int tid = threadIdx.x;
    int lane = tid & 31, warp = tid >> 5;
    int g = lane >> 2, j = lane & 3;
    int m_off = (warp & 1) * 32, n_off = (warp >> 1) * 32;
    int ar = tid >> 1, ac = (tid & 1) * 16;
    int m0 = blockIdx.y * 64, n0 = blockIdx.x * 64;
    bool bok = (n0 + ar) < V_;
    unsigned bsz = bok ? 16u : 0u;
    const float* abase = A + (long)(m0 + ar) * (2 * H_) + ac;
    const float* bbase = Bm + (long)(bok ? (n0 + ar) : 0) * (2 * H_) + ac;

    float cacc[2][4][4] = {};

#define LG_ISSUE(ST, KT) do {                                                \
        const float* as = abase + (KT) * 32;                                 \
        const float* bsp = bbase + (KT) * 32;                                \
        _Pragma("unroll")                                                    \
        for (int q = 0; q < 4; q++) {                                        \
            cpa16(sptr(&As[ST][ar][ac + q * 4]), as + q * 4);                \
            cpa16z(sptr(&Bs[ST][ar][ac + q * 4]), bsp + q * 4, bsz);         \
        }                                                                    \
        CPA_COMMIT();                                                        \
    } while (0)

    LG_ISSUE(0, 0);
    for (int kt = 0; kt < 16; kt++) {
        int cur = kt & 1, nxt = cur ^ 1;
        if (kt + 1 < 16) { LG_ISSUE(nxt, kt + 1); CPA_WAIT1(); }
        else { CPA_WAIT0(); }
        __syncthreads();
        const unsigned* AU = reinterpret_cast<const unsigned*>(As[cur]);
        const unsigned* BU = reinterpret_cast<const unsigned*>(Bs[cur]);
        MMA_RM32(AU, BU);
        __syncthreads();
    }
    #pragma unroll
    for (int mi = 0; mi < 2; mi++) {
        int rm = m0 + m_off + mi * 16;
        #pragma unroll
        for (int ni = 0; ni < 4; ni++) {
            int cn = n0 + n_off + ni * 8 + 2 * j;
            if (cn + 1 < V_) {
                float2 p0 = make_float2(cacc[mi][ni][0] + bias[cn], cacc[mi][ni][1] + bias[cn + 1]);
                float2 p1 = make_float2(cacc[mi][ni][2] + bias[cn], cacc[mi][ni][3] + bias[cn + 1]);
                *reinterpret_cast<float2*>(C + (long)(rm + g) * V_ + cn) = p0;
                *reinterpret_cast<float2*>(C + (long)(rm + g + 8) * V_ + cn) = p1;
            }
        }
    }
}

// ============================================================================
// Persistent LSTM, batch-parallel groups, k-split W-dedup (R12, measured good)
// ============================================================================
#define LSTM_GRID 128
#define WSTRIDE 129
#define LSTM_SMEM ((64 * WSTRIDE + 128) * 16 + 2 * 256 * 4)

__global__ void lstm_persist_k(const float* __restrict__ h0,
                               const float* __restrict__ c0,
                               const float* __restrict__ xproj,
                               const float* __restrict__ W_hh,
                               const float* __restrict__ b_hh,
                               float* __restrict__ h_glob,
                               float* __restrict__ comb,
                               float* __restrict__ o_hT,
                               float* __restrict__ o_cT) {
    extern __shared__ float4 sm4[];
    float4* w4s = sm4;                       // [64][WSTRIDE]
    float4* h4s = sm4 + 64 * WSTRIDE;        // [2][64]
    float*  part = (float*)(h4s + 128);      // [2][256]

    int tid = threadIdx.x;
    int grp = blockIdx.x >> 3;
    int blk = blockIdx.x & 7;

    const float4* W4 = reinterpret_cast<const float4*>(W_hh);
    for (int idx = tid; idx < 128 * 64; idx += 256) {
        int c = idx >> 6, k4 = idx & 63;
        int gcol = (c >> 5) * 256 + blk * 32 + (c & 31);
        w4s[k4 * WSTRIDE + c] = W4[(long)gcol * 64 + k4];
    }

    int pu = tid & 31, pbl = tid >> 5;
    int hh = blk * 32 + pu;
    int bb = grp * 2 + pbl;
    float c_reg = 0.f, bh0 = 0.f, bh1 = 0.f, bh2 = 0.f, bh3 = 0.f;
    if (tid < 64) {
        c_reg = c0[bb * H_ + hh];
        bh0 = b_hh[hh];           bh1 = b_hh[H_ + hh];
        bh2 = b_hh[2 * H_ + hh];  bh3 = b_hh[3 * H_ + hh];
    }

    int col = tid & 127, kh = tid >> 7;
    int kbase = kh * 32;
    volatile unsigned int* flags = g_flags;

    for (int t = 0; t < T_; t++) {
        if (t > 0) {
            if (tid < 8) {
                unsigned int tgt = (unsigned int)t;
                while (flags[grp * 8 + tid] < tgt) {}
            }
        }
        __syncthreads();

        const float* hsrc = (t == 0) ? h0 : h_glob;
        if (tid < 128) {
            int b = tid >> 6, k4 = tid & 63;
            h4s[b * 64 + k4] =
                __ldcg(reinterpret_cast<const float4*>(hsrc + (grp * 2 + b) * H_) + k4);
        }
        float xg0 = 0.f, xg1 = 0.f, xg2 = 0.f, xg3 = 0.f;
        if (tid < 64) {
            const float* xp = xproj + (long)(t * B_ + bb) * (4 * H_);
            xg0 = xp[hh]; xg1 = xp[H_ + hh]; xg2 = xp[2 * H_ + hh]; xg3 = xp[3 * H_ + hh];
        }
        __syncthreads();

        {
            float4 p0 = make_float4(0.f, 0.f, 0.f, 0.f);
            float4 p1 = make_float4(0.f, 0.f, 0.f, 0.f);
            const float4* hb0 = h4s;
            const float4* hb1 = h4s + 64;
            #pragma unroll 8
            for (int k4 = 0; k4 < 32; k4++) {
                float4 w = w4s[(kbase + k4) * WSTRIDE + col];
                float4 ha = hb0[kbase + k4];
                float4 hbv = hb1[kbase + k4];
                p0.x = fmaf(w.x, ha.x, p0.x);
                p0.y = fmaf(w.y, ha.y, p0.y);
                p0.z = fmaf(w.z, ha.z, p0.z);
                p0.w = fmaf(w.w, ha.w, p0.w);
                p1.x = fmaf(w.x, hbv.x, p1.x);
                p1.y = fmaf(w.y, hbv.y, p1.y);
                p1.z = fmaf(w.z, hbv.z, p1.z);
                p1.w = fmaf(w.w, hbv.w, p1.w);
            }
            part[kh * 256 + col * 2 + 0] = (p0.x + p0.y) + (p0.z + p0.w);
            part[kh * 256 + col * 2 + 1] = (p1.x + p1.y) + (p1.z + p1.w);
        }
        __syncthreads();

        if (tid < 64) {
            int i0 = (0 * 32 + pu) * 2 + pbl;
            int i1 = (1 * 32 + pu) * 2 + pbl;
            int i2 = (2 * 32 + pu) * 2 + pbl;
            int i3 = (3 * 32 + pu) * 2 + pbl;
            float gi = part[i0] + part[256 + i0] + xg0 + bh0;
            float gf = part[i1] + part[256 + i1] + xg1 + bh1;
            float gg = part[i2] + part[256 + i2] + xg2 + bh2;
            float go = part[i3] + part[256 + i3] + xg3 + bh3;
            float si = 1.f / (1.f + __expf(-gi));
            float sf = 1.f / (1.f + __expf(-gf));
            float so = 1.f / (1.f + __expf(-go));
            c_reg = sf * c_reg + si * tanhf(gg);
            float hn = so * tanhf(c_reg);
            h_glob[bb * H_ + hh] = hn;
            comb[(long)(t * B_ + bb) * (2 * H_) + H_ + hh] = hn;
            if (t == T_ - 1) {
                o_hT[bb * H_ + hh] = hn;
                o_cT[bb * H_ + hh] = c_reg;
            }
        }

        if (t < T_ - 1) {
            __syncthreads();
            if (tid == 0) {
                __threadfence();
                g_flags[blockIdx.x] = (unsigned int)(t + 1);
            }
        }
    }
}

// ========== fused attention: dec matvec + scores + softmax + context ========
__device__ __forceinline__ float tanh_fast(float x) {
    float y;
    asm("tanh.approx.f32 %0, %1;" : "=f"(y) : "f"(x));
    return y;
}

__global__ void attn_fused_k(const float* __restrict__ enc_t,
                             const float* __restrict__ Wd,
                             const float* __restrict__ bd,
                             const float* __restrict__ wa,
                             const float* __restrict__ ba,
                             const int* __restrict__ lens,
                             const float* __restrict__ enc,
                             float* __restrict__ comb,
                             float* __restrict__ ctx_out) {
    int t = blockIdx.x / B_, b = blockIdx.x % B_;
    __shared__ float out_sh[H_], dec_sh[H_], wa_sh[H_], sc[S_], red[S_];
    int tid = threadIdx.x;
    int wrp = tid >> 5, lane = tid & 31;

    out_sh[tid] = comb[(long)(t * B_ + b) * (2 * H_) + H_ + tid];
    wa_sh[tid] = wa[tid];
    __syncthreads();

    {
        const float4* o4 = reinterpret_cast<const float4*>(out_sh);
        float4 oa = o4[lane], ob = o4[lane + 32];
        #pragma unroll 4
        for (int i = 0; i < 32; i++) {
            int hh = wrp * 32 + i;
            const float4* wr = reinterpret_cast<const float4*>(Wd + (long)hh * H_);
            float4 w0 = wr[lane], w1 = wr[lane + 32];
            float s = oa.x * w0.x + oa.y * w0.y + oa.z * w0.z + oa.w * w0.w
                    + ob.x * w1.x + ob.y * w1.y + ob.z * w1.z + ob.w * w1.w;
            #pragma unroll
            for (int o = 16; o; o >>= 1) s += __shfl_xor_sync(0xffffffffu, s, o);
            if (lane == 0) dec_sh[hh] = s + bd[hh];
        }
    }
    __syncthreads();

    float bav = ba[0];
    for (int s = wrp; s < S_; s += 8) {
        const float* er = enc_t + (long)(s * B_ + b) * H_;
        float sum = 0.f;
        #pragma unroll
        for (int i = 0; i < 8; i++) {
            int hh = lane + 32 * i;
            sum += tanh_fast(er[hh] + dec_sh[hh]) * wa_sh[hh];
        }
        #pragma unroll
        for (int o = 16; o; o >>= 1) sum += __shfl_xor_sync(0xffffffffu, sum, o);
        if (lane == 0) sc[s] = sum + bav;
    }
    __syncthreads();

    int len = lens[b];
    float v = (tid < len) ? sc[tid] : -1e30f;
    red[tid] = v; __syncthreads();
    for (int o = 128; o; o >>= 1) { if (tid < o) red[tid] = fmaxf(red[tid], red[tid + o]); __syncthreads(); }
    float m = red[0]; __syncthreads();
    float e = __expf(v - m);
    red[tid] = e; __syncthreads();
    for (int o = 128; o; o >>= 1) { if (tid < o) red[tid] += red[tid + o]; __syncthreads(); }
    float p = e * __fdividef(1.f, red[0]);
    __syncthreads();
    sc[tid] = p;
    __syncthreads();

    float sum = 0.f;
    const float* ep = enc + b * H_ + tid;
    #pragma unroll 4
    for (int s = 0; s < S_; s++)
        sum = fmaf(sc[s], ep[(long)s * B_ * H_], sum);
    comb[(long)(t * B_ + b) * (2 * H_) + tid] = sum;
    ctx_out[(long)(b * T_ + t) * H_ + tid] = sum;
}

// ---------------- softmax over V=1000 ----------------
__global__ void softmax_v_k(const float* __restrict__ logits, float* __restrict__ out) {
    int tb = blockIdx.x;
    int tid = threadIdx.x;
    __shared__ float red[256];
    const float* row = logits + (long)tb * V_;
    float m = -1e30f;
    for (int v = tid; v < V_; v += 256) m = fmaxf(m, row[v]);
    red[tid] = m; __syncthreads();
    for (int o = 128; o; o >>= 1) { if (tid < o) red[tid] = fmaxf(red[tid], red[tid + o]); __syncthreads(); }
    m = red[0]; __syncthreads();
    float sum = 0.f;
    for (int v = tid; v < V_; v += 256) {
        float e = __expf(row[v] - m);
        out[(long)tb * V_ + v] = e;
        sum += e;
    }
    red[tid] = sum; __syncthreads();
    for (int o = 128; o; o >>= 1) { if (tid < o) red[tid] += red[tid + o]; __syncthreads(); }
    float inv = __fdividef(1.f, red[0]);
    for (int v = tid; v < V_; v += 256) out[(long)tb * V_ + v] *= inv;
}

// ---------------- host ----------------
extern "C" void kernel_launch(void* const* d_in, const int* in_sizes, int n_in,
                              void* d_out, int out_size) {
    const int*   tv      = (const int*)  d_in[0];
    const float* h0      = (const float*)d_in[1];
    const float* c0      = (const float*)d_in[2];
    const float* enc     = (const float*)d_in[3];
    const int*   lens    = (const int*)  d_in[4];
    const float* emb     = (const float*)d_in[5];
    const float* W_ih    = (const float*)d_in[6];
    const float* W_hh    = (const float*)d_in[7];
    const float* b_ih    = (const float*)d_in[8];
    const float* b_hh    = (const float*)d_in[9];
    const float* We      = (const float*)d_in[10];
    const float* be      = (const float*)d_in[11];
    const float* Wd      = (const float*)d_in[12];
    const float* bd      = (const float*)d_in[13];
    const float* wa      = (const float*)d_in[14];
    const float* ba      = (const float*)d_in[15];
    const float* W_out   = (const float*)d_in[16];
    const float* b_out   = (const float*)d_in[17];

    float* scratch = nullptr;
    cudaGetSymbolAddress((void**)&scratch, g_scratch);
    unsigned int* flagsp = nullptr;
    cudaGetSymbolAddress((void**)&flagsp, g_flags);

    float* s_xproj  = scratch + OFF_XPROJ;
    float* s_h      = scratch + OFF_H;
    float* s_enct   = scratch + OFF_ENCT;
    float* s_comb   = scratch + OFF_COMB;
    float* s_logits = scratch + OFF_LOGITS;

    float* o_prob = (float*)d_out;
    float* o_hT   = o_prob + (long)T_ * B_ * V_;
    float* o_cT   = o_hT + B_ * H_;
    float* o_ctx  = o_cT + B_ * H_;

    // 0) reset group-barrier flags
    cudaMemsetAsync(flagsp, 0, 128 * sizeof(unsigned int));

    // 1) dual tf32 GEMM (cp.async pipeline): xproj AND enc_t in one launch
    dual_gemm_k<<<640, 128>>>(emb, tv, W_ih, b_ih, s_xproj, enc, We, be, s_enct);

    // 2) persistent LSTM (k-split W-dedup)
    cudaFuncSetAttribute(lstm_persist_k, cudaFuncAttributeMaxDynamicSharedMemorySize, LSTM_SMEM);
    lstm_persist_k<<<LSTM_GRID, 256, LSTM_SMEM>>>(h0, c0, s_xproj, W_hh, b_hh,
                                                  s_h, s_comb, o_hT, o_cT);

    // 3) fused attention: dec matvec + scores + masked softmax + context
    attn_fused_k<<<T_ * B_, 256>>>(s_enct, Wd, bd, wa, ba, lens, enc, s_comb, o_ctx);

    // 4) logits = combined @ W_out^T + b_out : [512, 1000] (tf32, cp.async)
    logits_gemm_k<<<dim3(16, 8), 128>>>(s_comb, W_out, b_out, s_logits);

    // 5) softmax over V -> output_prob
    softmax_v_k<<<T_ * B_, 256>>>(s_logits, o_prob);
}

// round 16
// speedup vs baseline: 1.2619x; 1.0615x over previous
#include <cuda_runtime.h>
#include <cuda_bf16.h>
#include <math.h>

#define T_ 16
#define B_ 32
#define S_ 256
#define H_ 256
#define E_ 300
#define V_ 1000

// ---------------- scratch arena (floats) ----------------
#define OFF_XPROJ   153600      // [T*B, 4H] = 512*1024
#define OFF_H       710656      // 32*256
#define OFF_ENCT    727040      // 8192*256
#define OFF_COMB    3086336     // 512*512
#define OFF_LOGITS  3348480     // 512*1000
#define SCRATCH_N   3860480

__device__ float g_scratch[SCRATCH_N];
__device__ unsigned int g_flags[128];

// ==================== tf32 mma + cp.async helpers ====================
__device__ __forceinline__ void mma8(float* c, const unsigned* a, const unsigned* b) {
    asm("mma.sync.aligned.m16n8k8.row.col.f32.tf32.tf32.f32 "
        "{%0,%1,%2,%3}, {%4,%5,%6,%7}, {%8,%9}, {%0,%1,%2,%3};"
        : "+f"(c[0]), "+f"(c[1]), "+f"(c[2]), "+f"(c[3])
        : "r"(a[0]), "r"(a[1]), "r"(a[2]), "r"(a[3]), "r"(b[0]), "r"(b[1]));
}
__device__ __forceinline__ unsigned sptr(const void* p) {
    return (unsigned)__cvta_generic_to_shared(p);
}
__device__ __forceinline__ void cpa16(unsigned dst, const void* src) {
    asm volatile("cp.async.cg.shared.global [%0], [%1], 16;" :: "r"(dst), "l"(src));
}
__device__ __forceinline__ void cpa16z(unsigned dst, const void* src, unsigned sz) {
    asm volatile("cp.async.cg.shared.global [%0], [%1], 16, %2;" :: "r"(dst), "l"(src), "r"(sz));
}
#define CPA_COMMIT() asm volatile("cp.async.commit_group;" ::: "memory")
#define CPA_WAIT1()  asm volatile("cp.async.wait_group 1;" ::: "memory")
#define CPA_WAIT0()  asm volatile("cp.async.wait_group 0;" ::: "memory")

// 64x64x32 MMA tile from row-major smem [64][36] (raw fp32 bits as tf32).
// 4 warps, warp = 32x32 quadrant (mi=2, ni=4). Locals: g, j, m_off, n_off, cacc.
#define MMA_RM32(AU, BU)                                                     \
    _Pragma("unroll")                                                        \
    for (int s = 0; s < 4; s++) {                                            \
        unsigned af[2][4], bf[4][2];                                         \
        _Pragma("unroll")                                                    \
        for (int mi = 0; mi < 2; mi++) {                                     \
            int r0 = (m_off + mi * 16 + g) * 36 + s * 8 + j;                 \
            int r1 = (m_off + mi * 16 + g + 8) * 36 + s * 8 + j;             \
            af[mi][0] = (AU)[r0];                                            \
            af[mi][1] = (AU)[r1];                                            \
            af[mi][2] = (AU)[r0 + 4];                                        \
            af[mi][3] = (AU)[r1 + 4];                                        \
        }                                                                    \
        _Pragma("unroll")                                                    \
        for (int ni = 0; ni < 4; ni++) {                                     \
            int rb = (n_off + ni * 8 + g) * 36 + s * 8 + j;                  \
            bf[ni][0] = (BU)[rb];                                            \
            bf[ni][1] = (BU)[rb + 4];                                        \
        }                                                                    \
        _Pragma("unroll")                                                    \
        for (int mi = 0; mi < 2; mi++)                                       \
            _Pragma("unroll")                                                \
            for (int ni = 0; ni < 4; ni++)                                   \
                mma8(cacc[mi][ni], af[mi], bf[ni]);                          \
    }

// ============================================================================
// Dual tf32 GEMM with cp.async pipeline. 640 blocks x 128 threads.
// blocks [0,128):   xproj = emb[tv] @ W_ih^T + b_ih  (M=512,N=1024,K=300)
// blocks [128,640): enc_t = enc @ We^T + be          (M=8192,N=256,K=256)
// ============================================================================
__global__ void dual_gemm_k(const float* __restrict__ emb, const int* __restrict__ tv,
                            const float* __restrict__ W_ih, const float* __restrict__ b_ih,
                            float* __restrict__ xproj,
                            const float* __restrict__ enc, const float* __restrict__ We,
                            const float* __restrict__ be, float* __restrict__ enct) {
    __shared__ __align__(16) float As[2][64][36];
    __shared__ __align__(16) float Bs[2][64][36];
    __shared__ int rows_sh[64];

    int tid = threadIdx.x;
    int lane = tid & 31, warp = tid >> 5;
    int g = lane >> 2, j = lane & 3;
    int m_off = (warp & 1) * 32, n_off = (warp >> 1) * 32;
    int ar = tid >> 1, ac = (tid & 1) * 16;    // load row / float-offset in k-tile
    int bid = blockIdx.x;

    float cacc[2][4][4] = {};

    if (bid < 128) {
        // -------- xproj: K=300, 10 k-tiles (last ragged, zero-filled) -------
        int m0 = (bid >> 4) * 64, n0 = (bid & 15) * 64;
        if (tid < 64) rows_sh[tid] = tv[m0 + tid];
        __syncthreads();
        const float* abase = emb + (long)rows_sh[ar] * E_;
        const float* bbase = W_ih + (long)(n0 + ar) * E_;

#define XP_ISSUE(ST, KT) do {                                                \
            int kb = (KT) * 32 + ac;                                         \
            _Pragma("unroll")                                                \
            for (int q = 0; q < 4; q++) {                                    \
                int k = kb + q * 4;                                          \
                unsigned sz = (k < E_) ? 16u : 0u;                           \
                int ks = (k < E_) ? k : 0;                                   \
                cpa16z(sptr(&As[ST][ar][ac + q * 4]), abase + ks, sz);       \
                cpa16z(sptr(&Bs[ST][ar][ac + q * 4]), bbase + ks, sz);       \
            }                                                                \
            CPA_COMMIT();                                                    \
        } while (0)

        XP_ISSUE(0, 0);
        for (int kt = 0; kt < 10; kt++) {
            int cur = kt & 1, nxt = cur ^ 1;
            if (kt + 1 < 10) { XP_ISSUE(nxt, kt + 1); CPA_WAIT1(); }
            else { CPA_WAIT0(); }
            __syncthreads();
            const unsigned* AU = reinterpret_cast<const unsigned*>(As[cur]);
            const unsigned* BU = reinterpret_cast<const unsigned*>(Bs[cur]);
            MMA_RM32(AU, BU);
            __syncthreads();
        }
        #pragma unroll
        for (int mi = 0; mi < 2; mi++) {
            int rm = m0 + m_off + mi * 16;
            #pragma unroll
            for (int ni = 0; ni < 4; ni++) {
                int cn = n0 + n_off + ni * 8 + 2 * j;
                float2 p0 = make_float2(cacc[mi][ni][0] + b_ih[cn], cacc[mi][ni][1] + b_ih[cn + 1]);
                float2 p1 = make_float2(cacc[mi][ni][2] + b_ih[cn], cacc[mi][ni][3] + b_ih[cn + 1]);
                *reinterpret_cast<float2*>(xproj + (long)(rm + g) * (4 * H_) + cn) = p0;
                *reinterpret_cast<float2*>(xproj + (long)(rm + g + 8) * (4 * H_) + cn) = p1;
            }
        }
    } else {
        // -------- enc_t: K=256, 8 clean k-tiles ----------------------------
        int r2 = bid - 128;
        int m0 = (r2 >> 2) * 64, n0 = (r2 & 3) * 64;
        const float* abase = enc + (long)(m0 + ar) * H_ + ac;
        const float* bbase = We + (long)(n0 + ar) * H_ + ac;

#define EN_ISSUE(ST, KT) do {                                                \
            const float* as = abase + (KT) * 32;                             \
            const float* bsp = bbase + (KT) * 32;                            \
            _Pragma("unroll")                                                \
            for (int q = 0; q < 4; q++) {                                    \
                cpa16(sptr(&As[ST][ar][ac + q * 4]), as + q * 4);            \
                cpa16(sptr(&Bs[ST][ar][ac + q * 4]), bsp + q * 4);           \
            }                                                                \
            CPA_COMMIT();                                                    \
        } while (0)

        EN_ISSUE(0, 0);
        for (int kt = 0; kt < 8; kt++) {
            int cur = kt & 1, nxt = cur ^ 1;
            if (kt + 1 < 8) { EN_ISSUE(nxt, kt + 1); CPA_WAIT1(); }
            else { CPA_WAIT0(); }
            __syncthreads();
            const unsigned* AU = reinterpret_cast<const unsigned*>(As[cur]);
            const unsigned* BU = reinterpret_cast<const unsigned*>(Bs[cur]);
            MMA_RM32(AU, BU);
            __syncthreads();
        }
        #pragma unroll
        for (int mi = 0; mi < 2; mi++) {
            int rm = m0 + m_off + mi * 16;
            #pragma unroll
            for (int ni = 0; ni < 4; ni++) {
                int cn = n0 + n_off + ni * 8 + 2 * j;
                float2 p0 = make_float2(cacc[mi][ni][0] + be[cn], cacc[mi][ni][1] + be[cn + 1]);
                float2 p1 = make_float2(cacc[mi][ni][2] + be[cn], cacc[mi][ni][3] + be[cn + 1]);
                *reinterpret_cast<float2*>(enct + (long)(rm + g) * H_ + cn) = p0;
                *reinterpret_cast<float2*>(enct + (long)(rm + g + 8) * H_ + cn) = p1;
            }
        }
    }
}

// ============ logits tf32 GEMM (cp.async): M=512, N=1000, K=512 =============
__global__ void logits_gemm_k(const float* __restrict__ A,      // comb, lda=512
                              const float* __restrict__ Bm,     // W_out [1000,512]
                              const float* __restrict__ bias,
                              float* __restrict__ C) {          // [512,1000]
    __shared__ __align__(16) float As[2][64][36];
    __shared__ __align__(16) float Bs[2][64][36];

    int tid = threadIdx.x;
    int lane = tid & 31, warp = tid >> 5;
    int g = lane >> 2, j = lane & 3;
    int m_off = (warp & 1) * 32, n_off = (warp >> 1) * 32;
    int ar = tid >> 1, ac = (tid & 1) * 16;
    int m0 = blockIdx.y * 64, n0 = blockIdx.x * 64;
    bool bok = (n0 + ar) < V_;
    unsigned bsz = bok ? 16u : 0u;
    const float* abase = A + (long)(m0 + ar) * (2 * H_) + ac;
    const float* bbase = Bm + (long)(bok ? (n0 + ar) : 0) * (2 * H_) + ac;

    float cacc[2][4][4] = {};

#define LG_ISSUE(ST, KT) do {                                                \
        const float* as = abase + (KT) * 32;                                 \
        const float* bsp = bbase + (KT) * 32;                                \
        _Pragma("unroll")                                                    \
        for (int q = 0; q < 4; q++) {                                        \
            cpa16(sptr(&As[ST][ar][ac + q * 4]), as + q * 4);                \
            cpa16z(sptr(&Bs[ST][ar][ac + q * 4]), bsp + q * 4, bsz);         \
        }                                                                    \
        CPA_COMMIT();                                                        \
    } while (0)

    LG_ISSUE(0, 0);
    for (int kt = 0; kt < 16; kt++) {
        int cur = kt & 1, nxt = cur ^ 1;
        if (kt + 1 < 16) { LG_ISSUE(nxt, kt + 1); CPA_WAIT1(); }
        else { CPA_WAIT0(); }
        __syncthreads();
        const unsigned* AU = reinterpret_cast<const unsigned*>(As[cur]);
        const unsigned* BU = reinterpret_cast<const unsigned*>(Bs[cur]);
        MMA_RM32(AU, BU);
        __syncthreads();
    }
    #pragma unroll
    for (int mi = 0; mi < 2; mi++) {
        int rm = m0 + m_off + mi * 16;
        #pragma unroll
        for (int ni = 0; ni < 4; ni++) {
            int cn = n0 + n_off + ni * 8 + 2 * j;
            if (cn + 1 < V_) {
                float2 p0 = make_float2(cacc[mi][ni][0] + bias[cn], cacc[mi][ni][1] + bias[cn + 1]);
                float2 p1 = make_float2(cacc[mi][ni][2] + bias[cn], cacc[mi][ni][3] + bias[cn + 1]);
                *reinterpret_cast<float2*>(C + (long)(rm + g) * V_ + cn) = p0;
                *reinterpret_cast<float2*>(C + (long)(rm + g + 8) * V_ + cn) = p1;
            }
        }
    }
}

// ============================================================================
// Persistent LSTM, batch-parallel groups, W in REGISTERS.
// 128 blocks = 16 groups x 8. Block owns 128 gate cols for 2 batches.
// Thread = (col, k-half): W slice (32 float4) in registers, loaded once;
// h reads are warp-broadcast LDS (all lanes share kh). Inner loop is
// 2 broadcast LDS + 8 FFMA per k4 -> FMA-issue bound.
// ============================================================================
#define LSTM_GRID 128

__global__ void __launch_bounds__(256, 1)
lstm_persist_k(const float* __restrict__ h0,
               const float* __restrict__ c0,
               const float* __restrict__ xproj,
               const float* __restrict__ W_hh,
               const float* __restrict__ b_hh,
               float* __restrict__ h_glob,
               float* __restrict__ comb,
               float* __restrict__ o_hT,
               float* __restrict__ o_cT) {
    __shared__ float4 h4s[128];          // [2 batches][64]
    __shared__ float part[512];          // [2 kh][256]

    int tid = threadIdx.x;
    int grp = blockIdx.x >> 3;
    int blk = blockIdx.x & 7;

    int col = tid & 127, kh = tid >> 7;
    int kbase = kh * 32;                 // float4 k-offset

    // ---- W slice -> registers (once; constant across all steps) ----
    int gcol = (col >> 5) * 256 + blk * 32 + (col & 31);
    float4 wreg[32];
    {
        const float4* W4 = reinterpret_cast<const float4*>(W_hh) + (long)gcol * 64 + kbase;
        #pragma unroll
        for (int k4 = 0; k4 < 32; k4++) wreg[k4] = W4[k4];
    }

    // ---- pointwise state (tid < 64): pu = tid&31, pbl = tid>>5 ----
    int pu = tid & 31, pbl = tid >> 5;
    int hh = blk * 32 + pu;
    int bb = grp * 2 + pbl;
    float c_reg = 0.f, bh0 = 0.f, bh1 = 0.f, bh2 = 0.f, bh3 = 0.f;
    if (tid < 64) {
        c_reg = c0[bb * H_ + hh];
        bh0 = b_hh[hh];           bh1 = b_hh[H_ + hh];
        bh2 = b_hh[2 * H_ + hh];  bh3 = b_hh[3 * H_ + hh];
    }

    volatile unsigned int* flags = g_flags;

    for (int t = 0; t < T_; t++) {
        if (t > 0) {
            if (tid < 8) {
                unsigned int tgt = (unsigned int)t;
                while (flags[grp * 8 + tid] < tgt) {}
            }
        }
        __syncthreads();

        const float* hsrc = (t == 0) ? h0 : h_glob;
        if (tid < 128) {
            int b = tid >> 6, k4 = tid & 63;
            h4s[b * 64 + k4] =
                __ldcg(reinterpret_cast<const float4*>(hsrc + (grp * 2 + b) * H_) + k4);
        }
        float xg0 = 0.f, xg1 = 0.f, xg2 = 0.f, xg3 = 0.f;
        if (tid < 64) {
            const float* xp = xproj + (long)(t * B_ + bb) * (4 * H_);
            xg0 = xp[hh]; xg1 = xp[H_ + hh]; xg2 = xp[2 * H_ + hh]; xg3 = xp[3 * H_ + hh];
        }
        __syncthreads();

        // half-K dot products for both batches; W from registers, h broadcast
        {
            float4 p0 = make_float4(0.f, 0.f, 0.f, 0.f);
            float4 p1 = make_float4(0.f, 0.f, 0.f, 0.f);
            const float4* hb0 = h4s + kbase;
            const float4* hb1 = h4s + 64 + kbase;
            #pragma unroll
            for (int k4 = 0; k4 < 32; k4++) {
                float4 w = wreg[k4];
                float4 ha = hb0[k4];
                float4 hbv = hb1[k4];
                p0.x = fmaf(w.x, ha.x, p0.x);
                p0.y = fmaf(w.y, ha.y, p0.y);
                p0.z = fmaf(w.z, ha.z, p0.z);
                p0.w = fmaf(w.w, ha.w, p0.w);
                p1.x = fmaf(w.x, hbv.x, p1.x);
                p1.y = fmaf(w.y, hbv.y, p1.y);
                p1.z = fmaf(w.z, hbv.z, p1.z);
                p1.w = fmaf(w.w, hbv.w, p1.w);
            }
            part[kh * 256 + col * 2 + 0] = (p0.x + p0.y) + (p0.z + p0.w);
            part[kh * 256 + col * 2 + 1] = (p1.x + p1.y) + (p1.z + p1.w);
        }
        __syncthreads();

        if (tid < 64) {
            int i0 = (0 * 32 + pu) * 2 + pbl;
            int i1 = (1 * 32 + pu) * 2 + pbl;
            int i2 = (2 * 32 + pu) * 2 + pbl;
            int i3 = (3 * 32 + pu) * 2 + pbl;
            float gi = part[i0] + part[256 + i0] + xg0 + bh0;
            float gf = part[i1] + part[256 + i1] + xg1 + bh1;
            float gg = part[i2] + part[256 + i2] + xg2 + bh2;
            float go = part[i3] + part[256 + i3] + xg3 + bh3;
            float si = 1.f / (1.f + __expf(-gi));
            float sf = 1.f / (1.f + __expf(-gf));
            float so = 1.f / (1.f + __expf(-go));
            c_reg = sf * c_reg + si * tanhf(gg);
            float hn = so * tanhf(c_reg);
            h_glob[bb * H_ + hh] = hn;
            comb[(long)(t * B_ + bb) * (2 * H_) + H_ + hh] = hn;
            if (t == T_ - 1) {
                o_hT[bb * H_ + hh] = hn;
                o_cT[bb * H_ + hh] = c_reg;
            }
        }

        if (t < T_ - 1) {
            __syncthreads();
            if (tid == 0) {
                __threadfence();
                g_flags[blockIdx.x] = (unsigned int)(t + 1);
            }
        }
    }
}

// ========== fused attention: dec matvec + scores + softmax + context ========
__device__ __forceinline__ float tanh_fast(float x) {
    float y;
    asm("tanh.approx.f32 %0, %1;" : "=f"(y) : "f"(x));
    return y;
}

__global__ void attn_fused_k(const float* __restrict__ enc_t,
                             const float* __restrict__ Wd,
                             const float* __restrict__ bd,
                             const float* __restrict__ wa,
                             const float* __restrict__ ba,
                             const int* __restrict__ lens,
                             const float* __restrict__ enc,
                             float* __restrict__ comb,
                             float* __restrict__ ctx_out) {
    int t = blockIdx.x / B_, b = blockIdx.x % B_;
    __shared__ float out_sh[H_], dec_sh[H_], wa_sh[H_], sc[S_], red[S_];
    int tid = threadIdx.x;
    int wrp = tid >> 5, lane = tid & 31;

    out_sh[tid] = comb[(long)(t * B_ + b) * (2 * H_) + H_ + tid];
    wa_sh[tid] = wa[tid];
    __syncthreads();

    {
        const float4* o4 = reinterpret_cast<const float4*>(out_sh);
        float4 oa = o4[lane], ob = o4[lane + 32];
        #pragma unroll 4
        for (int i = 0; i < 32; i++) {
            int hh = wrp * 32 + i;
            const float4* wr = reinterpret_cast<const float4*>(Wd + (long)hh * H_);
            float4 w0 = wr[lane], w1 = wr[lane + 32];
            float s = oa.x * w0.x + oa.y * w0.y + oa.z * w0.z + oa.w * w0.w
                    + ob.x * w1.x + ob.y * w1.y + ob.z * w1.z + ob.w * w1.w;
            #pragma unroll
            for (int o = 16; o; o >>= 1) s += __shfl_xor_sync(0xffffffffu, s, o);
            if (lane == 0) dec_sh[hh] = s + bd[hh];
        }
    }
    __syncthreads();

    float bav = ba[0];
    for (int s = wrp; s < S_; s += 8) {
        const float* er = enc_t + (long)(s * B_ + b) * H_;
        float sum = 0.f;
        #pragma unroll
        for (int i = 0; i < 8; i++) {
            int hh = lane + 32 * i;
            sum += tanh_fast(er[hh] + dec_sh[hh]) * wa_sh[hh];
        }
        #pragma unroll
        for (int o = 16; o; o >>= 1) sum += __shfl_xor_sync(0xffffffffu, sum, o);
        if (lane == 0) sc[s] = sum + bav;
    }
    __syncthreads();

    int len = lens[b];
    float v = (tid < len) ? sc[tid] : -1e30f;
    red[tid] = v; __syncthreads();
    for (int o = 128; o; o >>= 1) { if (tid < o) red[tid] = fmaxf(red[tid], red[tid + o]); __syncthreads(); }
    float m = red[0]; __syncthreads();
    float e = __expf(v - m);
    red[tid] = e; __syncthreads();
    for (int o = 128; o; o >>= 1) { if (tid < o) red[tid] += red[tid + o]; __syncthreads(); }
    float p = e * __fdividef(1.f, red[0]);
    __syncthreads();
    sc[tid] = p;
    __syncthreads();

    float sum = 0.f;
    const float* ep = enc + b * H_ + tid;
    #pragma unroll 4
    for (int s = 0; s < S_; s++)
        sum = fmaf(sc[s], ep[(long)s * B_ * H_], sum);
    comb[(long)(t * B_ + b) * (2 * H_) + tid] = sum;
    ctx_out[(long)(b * T_ + t) * H_ + tid] = sum;
}

// ---------------- softmax over V=1000 ----------------
__global__ void softmax_v_k(const float* __restrict__ logits, float* __restrict__ out) {
    int tb = blockIdx.x;
    int tid = threadIdx.x;
    __shared__ float red[256];
    const float* row = logits + (long)tb * V_;
    float m = -1e30f;
    for (int v = tid; v < V_; v += 256) m = fmaxf(m, row[v]);
    red[tid] = m; __syncthreads();
    for (int o = 128; o; o >>= 1) { if (tid < o) red[tid] = fmaxf(red[tid], red[tid + o]); __syncthreads(); }
    m = red[0]; __syncthreads();
    float sum = 0.f;
    for (int v = tid; v < V_; v += 256) {
        float e = __expf(row[v] - m);
        out[(long)tb * V_ + v] = e;
        sum += e;
    }
    red[tid] = sum; __syncthreads();
    for (int o = 128; o; o >>= 1) { if (tid < o) red[tid] += red[tid + o]; __syncthreads(); }
    float inv = __fdividef(1.f, red[0]);
    for (int v = tid; v < V_; v += 256) out[(long)tb * V_ + v] *= inv;
}

// ---------------- host ----------------
extern "C" void kernel_launch(void* const* d_in, const int* in_sizes, int n_in,
                              void* d_out, int out_size) {
    const int*   tv      = (const int*)  d_in[0];
    const float* h0      = (const float*)d_in[1];
    const float* c0      = (const float*)d_in[2];
    const float* enc     = (const float*)d_in[3];
    const int*   lens    = (const int*)  d_in[4];
    const float* emb     = (const float*)d_in[5];
    const float* W_ih    = (const float*)d_in[6];
    const float* W_hh    = (const float*)d_in[7];
    const float* b_ih    = (const float*)d_in[8];
    const float* b_hh    = (const float*)d_in[9];
    const float* We      = (const float*)d_in[10];
    const float* be      = (const float*)d_in[11];
    const float* Wd      = (const float*)d_in[12];
    const float* bd      = (const float*)d_in[13];
    const float* wa      = (const float*)d_in[14];
    const float* ba      = (const float*)d_in[15];
    const float* W_out   = (const float*)d_in[16];
    const float* b_out   = (const float*)d_in[17];

    float* scratch = nullptr;
    cudaGetSymbolAddress((void**)&scratch, g_scratch);
    unsigned int* flagsp = nullptr;
    cudaGetSymbolAddress((void**)&flagsp, g_flags);

    float* s_xproj  = scratch + OFF_XPROJ;
    float* s_h      = scratch + OFF_H;
    float* s_enct   = scratch + OFF_ENCT;
    float* s_comb   = scratch + OFF_COMB;
    float* s_logits = scratch + OFF_LOGITS;

    float* o_prob = (float*)d_out;
    float* o_hT   = o_prob + (long)T_ * B_ * V_;
    float* o_cT   = o_hT + B_ * H_;
    float* o_ctx  = o_cT + B_ * H_;

    // 0) reset group-barrier flags
    cudaMemsetAsync(flagsp, 0, 128 * sizeof(unsigned int));

    // 1) dual tf32 GEMM (cp.async pipeline): xproj AND enc_t in one launch
    dual_gemm_k<<<640, 128>>>(emb, tv, W_ih, b_ih, s_xproj, enc, We, be, s_enct);

    // 2) persistent LSTM (W in registers, broadcast h)
    lstm_persist_k<<<LSTM_GRID, 256>>>(h0, c0, s_xproj, W_hh, b_hh,
                                       s_h, s_comb, o_hT, o_cT);

    // 3) fused attention: dec matvec + scores + masked softmax + context
    attn_fused_k<<<T_ * B_, 256>>>(s_enct, Wd, bd, wa, ba, lens, enc, s_comb, o_ctx);

    // 4) logits = combined @ W_out^T + b_out : [512, 1000] (tf32, cp.async)
    logits_gemm_k<<<dim3(16, 8), 128>>>(s_comb, W_out, b_out, s_logits);

    // 5) softmax over V -> output_prob
    softmax_v_k<<<T_ * B_, 256>>>(s_logits, o_prob);
}